// round 10
// baseline (speedup 1.0000x reference)
#include <cuda_runtime.h>
#include <cuda_bf16.h>
#include <cstdint>

typedef unsigned int u32; typedef unsigned short u16;

// AttentionMV B=T=1024, E=128. mma.sync bf16 3-pass split.
// R10: single barrier/tile (double-buffered m-frags), bias reg-prefetch,
//      interleaved hi/lo m-frags (LDS.128), MUFU-free tanh.
//  GEMM1 (per 64-t tile): D1[f][t] = sum_e WT[f][e]*m[t][e]
//  u = tanh(D1+b) -> bf16 hi/lo in registers (accum layout == B-frag layout)
//  GEMM2: pre[e][f] += sum_t vT[e][t]*u[t][f]  (reg accum over all tiles)

constexpr int NT = 256;
constexpr u32 WFH = 0;          // W frag hi 32KB
constexpr u32 WFL = 32768;      // W frag lo 32KB
constexpr u32 MF0 = 65536;      // m frag buf0 (hi/lo interleaved) 32KB
constexpr u32 MF1 = 98304;      // m frag buf1 32KB
constexpr u32 VT0 = 131072;     // vT frag buf0 (hi 16K + lo 16K)
constexpr u32 VT1 = 163840;
constexpr u32 SP_OFF = 196608;  // 8*128 f32
constexpr u32 CF_OFF = 200704;  // 128 f32
constexpr u32 SMEM_BYTES = 201728;
// epilogue aliases (all source regions dead after final barrier)
constexpr u32 P_OFF  = 0;       // 128*132*4 = 67584 B
constexpr u32 EX_OFF = 98304;   // 67584 B

__device__ u16 g_vtFH[131072];   // vT A-frag images, 16KB per tile
__device__ u16 g_vtFL[131072];

__device__ __forceinline__ float trunc_hi(float x){
    return __uint_as_float(__float_as_uint(x) & 0xffff0000u);
}
__device__ __forceinline__ u32 cvt_bf16x2(float hiArg, float loArg){
    u32 d; asm("cvt.rn.bf16x2.f32 %0, %1, %2;" : "=r"(d) : "f"(hiArg), "f"(loArg));
    return d;
}
// FMA-only tanh: tanh(x) = sign(x)*(1 - 2/(2^y + 1)), y = 2|x|*log2(e), y<=16.
__device__ __forceinline__ float tanh_fma(float x){
    float y = fminf(fabsf(x)*2.885390082f, 16.0f);
    float z = y + 12582912.0f;                     // round-to-nearest trick
    int   n = __float_as_int(z) - 0x4B400000;
    float r = y - (z - 12582912.0f);               // r in [-0.5, 0.5]
    float p = 0.0013333558f;
    p = fmaf(p, r, 0.0096181291f); p = fmaf(p, r, 0.0555041087f);
    p = fmaf(p, r, 0.2402265070f); p = fmaf(p, r, 0.6931471806f);
    p = fmaf(p, r, 1.0f);
    float E = __int_as_float((n+127)<<23) * p;     // 2^y
    float d = E + 1.0f;
    float q = __int_as_float(0x7EF311C3 - __float_as_int(d));
    q = q*fmaf(-d,q,2.0f); q = q*fmaf(-d,q,2.0f); q = q*fmaf(-d,q,2.0f);
    return copysignf(fmaf(-2.0f, q, 1.0f), x);
}
__device__ __forceinline__ void mma16816(float* d, u32 a0,u32 a1,u32 a2,u32 a3,
                                         u32 b0,u32 b1){
    asm volatile("mma.sync.aligned.m16n8k16.row.col.f32.bf16.bf16.f32 "
        "{%0,%1,%2,%3}, {%4,%5,%6,%7}, {%8,%9}, {%0,%1,%2,%3};"
        : "+f"(d[0]),"+f"(d[1]),"+f"(d[2]),"+f"(d[3])
        : "r"(a0),"r"(a1),"r"(a2),"r"(a3),"r"(b0),"r"(b1));
}
__device__ __forceinline__ u32 smem_u32(const void* p){
    u32 a; asm("{ .reg .u64 t; cvta.to.shared.u64 t, %1; cvt.u32.u64 %0, t; }"
               : "=r"(a) : "l"(p));
    return a;
}
__device__ __forceinline__ void cp16(u32 dst, const void* src){
    asm volatile("cp.async.ca.shared.global [%0], [%1], 16;" :: "r"(dst), "l"(src));
}

// vT A-frag prep (same as R9): a-frag for A[m=e][k=t]
__global__ void vt_prep(const float* __restrict__ gv){
    int t = blockIdx.x, e = threadIdx.x;
    float x = gv[t*128 + e];
    u16 hi = (u16)(__float_as_uint(x) >> 16);
    u16 lo = __bfloat16_as_ushort(__float2bfloat16(x - trunc_hi(x)));
    int tile = t>>6, s = (t>>4)&3, tr = t&15;
    int kh = tr>>3, rs = (tr&7)>>1, byt = tr&1;
    int i = e>>4, eq = e&15, rh = eq>>3, q = eq&7;
    int reg = rh + 2*kh, lane = q*4 + rs;
    int idx = ((tile*32 + i*4 + s)*32 + lane)*8 + reg*2 + byt;
    g_vtFH[idx] = hi; g_vtFL[idx] = lo;
}

__global__ __launch_bounds__(NT,1)
void attn_mma(const float* __restrict__ gm, const float* __restrict__ gW,
              const float* __restrict__ gb, float* __restrict__ gout)
{
    extern __shared__ char sm[];
    const u32 sbase = smem_u32(sm);
    const int tid=threadIdx.x, lane=tid&31, w=tid>>5, bb=blockIdx.x;
    const int q=lane>>2, r2=(lane&3)*2;
    const float* Wb = gW + (size_t)bb*16384;
    const float4* mb4 = (const float4*)(gm + (size_t)bb*131072);

    // writer-side m-frag constants
    const int m_ks = lane>>2, m_r = (lane>>1)&1;
    const int m_l  = w*4 + (lane&1)*2;          // reader frag-lane for pair A

    // ---- W -> A-frag layout (unchanged from R9)
    for (int it=0; it<64; it++){
        int idx = it*NT + tid;
        int e = idx>>7, f = idx&127;
        float x = __ldg(Wb + idx);
        u16 hi = (u16)(__float_as_uint(x) >> 16);
        u16 lo = __bfloat16_as_ushort(__float2bfloat16(x - trunc_hi(x)));
        int w2=f>>4, fr=f&15, rh=fr>>3, qq=fr&7;
        int ks=e>>4, er=e&15, kh=er>>3, rs=(er&7)>>1, byt=er&1;
        u32 off = (u32)(((w2*8+ks)*32 + qq*4 + rs)*16 + (rh + 2*kh)*4 + byt*2);
        *(u16*)(sm + WFH + off) = hi;
        *(u16*)(sm + WFL + off) = lo;
    }

    float s4[4]={0,0,0,0};
    float4 mreg[8];

    // m-split into a frag buffer: blocks (nb=j, ks), 128 u32/block,
    // slot layout per reader-lane: [b0h, b1h, b0l, b1l], rotated by ks*16.
    auto msplit = [&](u32 mf){
        #pragma unroll
        for (int j=0;j<8;j++){
            float4 x = mreg[j];
            s4[0]+=x.x; s4[1]+=x.y; s4[2]+=x.z; s4[3]+=x.w;
            u32 hA = __byte_perm(__float_as_uint(x.x), __float_as_uint(x.y), 0x7632);
            u32 hB = __byte_perm(__float_as_uint(x.z), __float_as_uint(x.w), 0x7632);
            float l0 = x.x - trunc_hi(x.x), l1 = x.y - trunc_hi(x.y);
            float l2 = x.z - trunc_hi(x.z), l3 = x.w - trunc_hi(x.w);
            u32 lA = cvt_bf16x2(l1, l0), lB = cvt_bf16x2(l3, l2);
            u32 blk = mf + (u32)(j*8 + m_ks)*512;
            u32 iA = (u32)((m_l*4     + m_r + m_ks*16) & 127);
            u32 iB = (u32)(((m_l+1)*4 + m_r + m_ks*16) & 127);
            *(u32*)(sm + blk + iA*4)     = hA;
            *(u32*)(sm + blk + iA*4 + 8) = lA;
            *(u32*)(sm + blk + iB*4)     = hB;
            *(u32*)(sm + blk + iB*4 + 8) = lB;
        }
    };
    auto cpvt = [&](int tile, u32 dst){
        const char* srcH = (const char*)g_vtFH + (size_t)tile*16384;
        const char* srcL = (const char*)g_vtFL + (size_t)tile*16384;
        #pragma unroll
        for (int k2=0;k2<4;k2++){
            cp16(sbase + dst + tid*64 + k2*16,         srcH + tid*64 + k2*16);
            cp16(sbase + dst + 16384 + tid*64 + k2*16, srcL + tid*64 + k2*16);
        }
        asm volatile("cp.async.commit_group;");
    };

    // ---- prologue: split m(0) into MF0, preload m(1), cp vT(0)
    #pragma unroll
    for (int j=0;j<8;j++) mreg[j] = __ldg(mb4 + j*NT + tid);
    msplit(MF0);
    #pragma unroll
    for (int j=0;j<8;j++) mreg[j] = __ldg(mb4 + 2048 + j*NT + tid);
    cpvt(0, VT0);

    float pre[8][2][4];
    #pragma unroll
    for (int i=0;i<8;i++)
        #pragma unroll
        for (int fb=0;fb<2;fb++)
            #pragma unroll
            for (int j2=0;j2<4;j2++) pre[i][fb][j2]=0.f;

    __syncthreads();   // W frags + MF0 visible

    const int f0 = w*16 + q;

    for (int tile=0; tile<16; tile++){
        const u32 MFp = (tile&1) ? MF1 : MF0;
        const u32 VTp = (tile&1) ? VT1 : VT0;

        // A ---- bias prefetch (independent LDGs, consumed after GEMM1)
        float bl[32];
        #pragma unroll
        for (int nb=0;nb<8;nb++){
            const float* bp = gb + (size_t)(tile*64 + nb*8 + r2)*128;
            bl[nb*4+0]=__ldg(bp+f0);     bl[nb*4+1]=__ldg(bp+128+f0);
            bl[nb*4+2]=__ldg(bp+f0+8);   bl[nb*4+3]=__ldg(bp+128+f0+8);
        }

        // B ---- GEMM1: warp w -> f rows w*16..+15, t cols 0..63
        float d1[8][4];
        #pragma unroll
        for (int nb=0;nb<8;nb++){ d1[nb][0]=0;d1[nb][1]=0;d1[nb][2]=0;d1[nb][3]=0; }
        #pragma unroll
        for (int ks=0;ks<8;ks++){
            uint4 ahv = *(const uint4*)(sm + WFH + (u32)(((w*8+ks)*32+lane)*16));
            uint4 alv = *(const uint4*)(sm + WFL + (u32)(((w*8+ks)*32+lane)*16));
            uint4 bf[8];
            u32 bpos = (u32)((lane*4 + ks*16) & 127)*4;
            #pragma unroll
            for (int nb=0;nb<8;nb++)
                bf[nb] = *(const uint4*)(sm + MFp + (u32)(nb*8+ks)*512 + bpos);
            #pragma unroll
            for (int nb=0;nb<8;nb++)
                mma16816(d1[nb], ahv.x,ahv.y,ahv.z,ahv.w, bf[nb].x, bf[nb].y);
            #pragma unroll
            for (int nb=0;nb<8;nb++)
                mma16816(d1[nb], ahv.x,ahv.y,ahv.z,ahv.w, bf[nb].z, bf[nb].w);
            #pragma unroll
            for (int nb=0;nb<8;nb++)
                mma16816(d1[nb], alv.x,alv.y,alv.z,alv.w, bf[nb].x, bf[nb].y);
        }

        // C ---- bias + tanh (FMA-only) + bf16 split, registers only
        u32 uh[8][2], ul[8][2];
        #pragma unroll
        for (int nb=0;nb<8;nb++){
            float u0=tanh_fma(d1[nb][0]+bl[nb*4+0]);
            float u1=tanh_fma(d1[nb][1]+bl[nb*4+1]);
            float u2=tanh_fma(d1[nb][2]+bl[nb*4+2]);
            float u3=tanh_fma(d1[nb][3]+bl[nb*4+3]);
            uh[nb][0] = __byte_perm(__float_as_uint(u0), __float_as_uint(u1), 0x7632);
            uh[nb][1] = __byte_perm(__float_as_uint(u2), __float_as_uint(u3), 0x7632);
            ul[nb][0] = cvt_bf16x2(u1 - trunc_hi(u1), u0 - trunc_hi(u0));
            ul[nb][1] = cvt_bf16x2(u3 - trunc_hi(u3), u2 - trunc_hi(u2));
        }

        // D ---- split m(tile+1) into other MF buffer; preload m(tile+2)
        if (tile < 15){
            msplit((tile&1) ? MF0 : MF1);
            if (tile < 14){
                #pragma unroll
                for (int j=0;j<8;j++)
                    mreg[j] = __ldg(mb4 + (tile+2)*2048 + j*NT + tid);
            }
        }

        // E ---- vT(tile) must have landed
        asm volatile("cp.async.wait_group 0;");
        // F ---- the one barrier per tile
        __syncthreads();
        // G ---- prefetch vT(tile+1) (safe: all warps past GEMM2(tile-1))
        if (tile < 15) cpvt(tile+1, (tile&1) ? VT0 : VT1);

        // H ---- GEMM2: pass-major, i-quads
        #pragma unroll
        for (int s=0;s<4;s++){
            #pragma unroll
            for (int iq=0;iq<2;iq++){
                u32 ah[4][4], al[4][4];
                #pragma unroll
                for (int ii=0;ii<4;ii++){
                    int i = iq*4+ii;
                    uint4 a4 = *(const uint4*)(sm + VTp + (u32)(((i*4+s)*32+lane)*16));
                    ah[ii][0]=a4.x; ah[ii][1]=a4.y; ah[ii][2]=a4.z; ah[ii][3]=a4.w;
                    uint4 a5 = *(const uint4*)(sm + VTp + 16384 + (u32)(((i*4+s)*32+lane)*16));
                    al[ii][0]=a5.x; al[ii][1]=a5.y; al[ii][2]=a5.z; al[ii][3]=a5.w;
                }
                #pragma unroll
                for (int ii=0;ii<4;ii++)
                    #pragma unroll
                    for (int fb=0;fb<2;fb++)
                        mma16816(pre[iq*4+ii][fb], ah[ii][0],ah[ii][1],ah[ii][2],ah[ii][3],
                                 uh[2*s][fb], uh[2*s+1][fb]);
                #pragma unroll
                for (int ii=0;ii<4;ii++)
                    #pragma unroll
                    for (int fb=0;fb<2;fb++)
                        mma16816(pre[iq*4+ii][fb], ah[ii][0],ah[ii][1],ah[ii][2],ah[ii][3],
                                 ul[2*s][fb], ul[2*s+1][fb]);
                #pragma unroll
                for (int ii=0;ii<4;ii++)
                    #pragma unroll
                    for (int fb=0;fb<2;fb++)
                        mma16816(pre[iq*4+ii][fb], al[ii][0],al[ii][1],al[ii][2],al[ii][3],
                                 uh[2*s][fb], uh[2*s+1][fb]);
            }
        }
    }
    __syncthreads();   // all GEMM2/WF/VT reads done before epilogue aliasing

    // ---- epilogue
    float* P = (float*)(sm + P_OFF);
    #pragma unroll
    for (int i=0;i<8;i++)
        #pragma unroll
        for (int fb=0;fb<2;fb++){
            int e0 = i*16+q, ff = w*16+fb*8+r2;
            P[e0*132+ff]       = pre[i][fb][0];
            P[e0*132+ff+1]     = pre[i][fb][1];
            P[(e0+8)*132+ff]   = pre[i][fb][2];
            P[(e0+8)*132+ff+1] = pre[i][fb][3];
        }
    float* SP=(float*)(sm+SP_OFF);
    *(float4*)(SP + w*128 + lane*4) = make_float4(s4[0],s4[1],s4[2],s4[3]);
    __syncthreads();

    float* EX=(float*)(sm+EX_OFF);
    float* CF=(float*)(sm+CF_OFF);
    if (tid<128){
        int e=tid;
        float ss=0;
        #pragma unroll
        for (int ww=0;ww<8;ww++) ss+=SP[ww*128+e];
        float mx=-1e30f;
        #pragma unroll 8
        for (int f=0;f<128;f++) mx=fmaxf(mx,P[e*132+f]);
        float sum=0;
        #pragma unroll 4
        for (int f=0;f<128;f++){
            float ex=__expf(P[e*132+f]-mx);
            sum+=ex; EX[f*132+e]=ex;
        }
        CF[e]=ss*__fdividef(1.f,sum);
    }
    __syncthreads();
    if (tid<128){
        int f=tid; float acc=0;
        #pragma unroll 8
        for (int e=0;e<128;e++) acc=fmaf(CF[e],EX[f*132+e],acc);
        gout[(size_t)bb*128+f]=acc;
    }
}

extern "C" void kernel_launch(void* const* d_in, const int* in_sizes, int n_in,
                              void* d_out, int out_size) {
    const float* m = (const float*)d_in[0];
    const float* v = (const float*)d_in[1];
    const float* W = (const float*)d_in[2];
    const float* b = (const float*)d_in[3];
    float* out = (float*)d_out;

    vt_prep<<<1024, 128>>>(v);
    cudaFuncSetAttribute(attn_mma, cudaFuncAttributeMaxDynamicSharedMemorySize,
                         (int)SMEM_BYTES);
    attn_mma<<<1024, NT, SMEM_BYTES>>>(m, W, b, out);
}